// round 6
// baseline (speedup 1.0000x reference)
#include <cuda_runtime.h>
#include <math_constants.h>

// KNN max-pooling: out[q, :] = max over j in 0..15 of feat[idx[q, j], :]
// feat: [100000, 64] f32, idx: [100000, 16] int32, out: [100000, 64] f32.
//
// 16 threads per query (2 queries/warp). Lane l owns channels [4l, 4l+4) as a
// float4. Neighbor row offsets broadcast via 32-bit shfl in the 16-lane
// segment; gathers are fully-coalesced LDG.128 covering each 256 B row.
//
// R4/R5 change (unmeasured in R5 due to broker failure; re-submitting):
// explicit MLP. Two batches of 8 resident float4 loads with the register cap
// raised to 64 (__launch_bounds__(256, 4)) so the scoreboard can keep ~8
// gather loads in flight per thread instead of ~4 at regs=32. Trades
// occupancy (88% -> ~50%) for memory-level parallelism; R3 measurement showed
// latency-bound behavior (L2 66%, L1 59%, DRAM 16%, issue 22%).
// Output stored with streaming hint (__stcs): never re-read, keep L2 for feat.

#define NSAMPLE 16
#define C4 16  // 64 channels / 4 per float4

__device__ __forceinline__ void fmax4(float4& a, const float4& b) {
    a.x = fmaxf(a.x, b.x);
    a.y = fmaxf(a.y, b.y);
    a.z = fmaxf(a.z, b.z);
    a.w = fmaxf(a.w, b.w);
}

__global__ void __launch_bounds__(256, 4) knn_pool_kernel(
    const float4* __restrict__ feat,   // [N, 16] float4
    const int* __restrict__ idx,       // [M, 16] int32
    float4* __restrict__ out,          // [M, 16] float4
    int M)
{
    int tid = blockIdx.x * blockDim.x + threadIdx.x;
    int q = tid >> 4;
    int lane = tid & 15;
    if (q >= M) return;

    // Coalesced idx load; pre-scale to float4 row offset (fits in 32 bits).
    int my_off = __ldg(&idx[q * NSAMPLE + lane]) * C4;

    float4 v[8];

    // Batch 1: rows 0..7 all in flight before any consumption.
    #pragma unroll
    for (int j = 0; j < 8; ++j) {
        int nb = __shfl_sync(0xFFFFFFFFu, my_off, j, 16);
        v[j] = feat[nb + lane];
    }

    // Reduce batch 1 (tree).
    fmax4(v[0], v[4]); fmax4(v[1], v[5]); fmax4(v[2], v[6]); fmax4(v[3], v[7]);
    fmax4(v[0], v[2]); fmax4(v[1], v[3]);
    fmax4(v[0], v[1]);
    float4 acc = v[0];

    // Batch 2: rows 8..15.
    #pragma unroll
    for (int j = 0; j < 8; ++j) {
        int nb = __shfl_sync(0xFFFFFFFFu, my_off, 8 + j, 16);
        v[j] = feat[nb + lane];
    }

    fmax4(v[0], v[4]); fmax4(v[1], v[5]); fmax4(v[2], v[6]); fmax4(v[3], v[7]);
    fmax4(v[0], v[2]); fmax4(v[1], v[3]);
    fmax4(v[0], v[1]);
    fmax4(acc, v[0]);

    // Streaming store: output is write-once, don't pollute L2.
    __stcs(&out[q * C4 + lane], acc);
}

extern "C" void kernel_launch(void* const* d_in, const int* in_sizes, int n_in,
                              void* d_out, int out_size)
{
    const float4* feat = (const float4*)d_in[0];
    const int* idx     = (const int*)d_in[1];
    float4* out        = (float4*)d_out;

    int M = in_sizes[1] / NSAMPLE;  // idx has M*16 elements

    int total_threads = M * 16;
    int block = 256;
    int grid = (total_threads + block - 1) / block;
    knn_pool_kernel<<<grid, block>>>(feat, idx, out, M);
}

// round 10
// speedup vs baseline: 1.0932x; 1.0932x over previous
#include <cuda_runtime.h>
#include <math_constants.h>

// KNN max-pooling: out[q, :] = max over j in 0..15 of feat[idx[q, j], :]
// feat: [100000, 64] f32, idx: [100000, 16] int32, out: [100000, 64] f32.
//
// 16 threads per query (2 queries/warp). Lane l owns channels [4l, 4l+4) as a
// float4. Neighbor row offsets broadcast via 32-bit shfl in the 16-lane
// segment; gathers are fully-coalesced LDG.128 covering each 256 B row.
//
// R7: middle occupancy/MLP point. R3 (regs=32, occ=88%) = 25.1us;
// R6 (regs=64, occ=42%) = 27.4us. Cap regs at 42 via __launch_bounds__(256,6)
// -> occ ~62-75%, ~5-6 loads in flight per thread. Plus cache hygiene:
// feat loads ld.global.nc.L1::evict_last (only feat deserves L1/L2 residency),
// output stores streaming (__stcs).

#define NSAMPLE 16
#define C4 16  // 64 channels / 4 per float4

__device__ __forceinline__ float4 ldg_evict_last(const float4* p) {
    float4 v;
    asm("ld.global.nc.L1::evict_last.v4.f32 {%0,%1,%2,%3}, [%4];"
        : "=f"(v.x), "=f"(v.y), "=f"(v.z), "=f"(v.w)
        : "l"(p));
    return v;
}

__device__ __forceinline__ void fmax4(float4& a, const float4& b) {
    a.x = fmaxf(a.x, b.x);
    a.y = fmaxf(a.y, b.y);
    a.z = fmaxf(a.z, b.z);
    a.w = fmaxf(a.w, b.w);
}

__global__ void __launch_bounds__(256, 6) knn_pool_kernel(
    const float4* __restrict__ feat,   // [N, 16] float4
    const int* __restrict__ idx,       // [M, 16] int32
    float4* __restrict__ out,          // [M, 16] float4
    int M)
{
    int tid = blockIdx.x * blockDim.x + threadIdx.x;
    int q = tid >> 4;
    int lane = tid & 15;
    if (q >= M) return;

    // Coalesced idx load; pre-scale to float4 row offset (fits in 32 bits).
    int my_off = __ldg(&idx[q * NSAMPLE + lane]) * C4;

    float4 m;
    m.x = -CUDART_INF_F; m.y = -CUDART_INF_F;
    m.z = -CUDART_INF_F; m.w = -CUDART_INF_F;

    // Fully unrolled; ptxas batches loads up to the 42-reg budget (~5-6 in
    // flight), balancing MLP against occupancy.
    #pragma unroll
    for (int j = 0; j < NSAMPLE; ++j) {
        int nb = __shfl_sync(0xFFFFFFFFu, my_off, j, 16);
        float4 v = ldg_evict_last(&feat[nb + lane]);
        fmax4(m, v);
    }

    // Streaming store: output is write-once, don't displace feat in L2.
    __stcs(&out[q * C4 + lane], m);
}

extern "C" void kernel_launch(void* const* d_in, const int* in_sizes, int n_in,
                              void* d_out, int out_size)
{
    const float4* feat = (const float4*)d_in[0];
    const int* idx     = (const int*)d_in[1];
    float4* out        = (float4*)d_out;

    int M = in_sizes[1] / NSAMPLE;  // idx has M*16 elements

    int total_threads = M * 16;
    int block = 256;
    int grid = (total_threads + block - 1) / block;
    knn_pool_kernel<<<grid, block>>>(feat, idx, out, M);
}